// round 5
// baseline (speedup 1.0000x reference)
#include <cuda_runtime.h>
#include <cuda_bf16.h>
#include <cstdint>

#define NN 512

// ---------------- scratch (no allocations allowed) ----------------
__device__ float g_A[NN * 256];
__device__ float g_B[NN * 256];
__device__ float g_S2a[NN * 256];
__device__ float g_S2b[NN * 256];
__device__ float g_summ[NN * 128];
__device__ float g_g1[NN * 256];
__device__ float g_g2[NN * 256];
__device__ float g_ig[NN * 128];
__device__ float g_gates[NN * 512];
__device__ float g_o1[NN * 256];
// Wf2 split into bf16 hi/lo, chunked layout [kc][n][64]
__device__ uint4 g_Whi4[8192];
__device__ uint4 g_Wlo4[8192];

// ================= helpers =================
__device__ __forceinline__ uint32_t smem_u32(const void* p) {
    uint32_t a;
    asm("{ .reg .u64 t; cvta.to.shared.u64 t, %1; cvt.u32.u64 %0, t; }" : "=r"(a) : "l"(p));
    return a;
}

__device__ __forceinline__ void ldsm4(uint32_t (&r)[4], uint32_t addr) {
    asm volatile("ldmatrix.sync.aligned.m8n8.x4.shared.b16 {%0,%1,%2,%3}, [%4];"
        : "=r"(r[0]), "=r"(r[1]), "=r"(r[2]), "=r"(r[3]) : "r"(addr));
}

__device__ __forceinline__ void mma16816(float (&d)[4], const uint32_t (&a)[4],
                                         uint32_t b0, uint32_t b1) {
    asm volatile(
        "mma.sync.aligned.m16n8k16.row.col.f32.bf16.bf16.f32 "
        "{%0,%1,%2,%3}, {%4,%5,%6,%7}, {%8,%9}, {%0,%1,%2,%3};"
        : "+f"(d[0]), "+f"(d[1]), "+f"(d[2]), "+f"(d[3])
        : "r"(a[0]), "r"(a[1]), "r"(a[2]), "r"(a[3]), "r"(b0), "r"(b1));
}

__device__ __forceinline__ uint32_t pack_rn2(float f0, float f1) {
    uint32_t r; asm("cvt.rn.bf16x2.f32 %0, %1, %2;" : "=r"(r) : "f"(f1), "f"(f0));
    return r;
}

#define CP_ASYNC16(dst, src) \
    asm volatile("cp.async.cg.shared.global [%0], [%1], 16;" :: "r"(dst), "l"(src))
#define CP_COMMIT() asm volatile("cp.async.commit_group;" ::: "memory")
#define CP_WAIT0()  asm volatile("cp.async.wait_group 0;"  ::: "memory")

// ================= pair kernel smem layout (byte offsets, double-buffered) =================
#define OFF_AHI 0u         // 2 x 16384
#define OFF_ALO 32768u     // 2 x 16384
#define OFF_WHI 65536u     // 2 x 32768
#define OFF_WLO 131072u    // 2 x 32768
#define OFF_BB  196608u    // 1024
#define OFF_B2  197632u    // 1024
#define OFF_RED 198656u    // 2048
#define PAIR_DYN_SMEM (200704u + 128u)

// ---------------- pairwise HMMA kernel ----------------
// grid (512, 2): j = blockIdx.x, half = blockIdx.y (i-rows [half*256, half*256+256))
// S2half[j,n] = sum_{i in half} relu( relu(A[i]+B[j]+bf1) @ Wf2^T + bf2 )[n]
// 3-pass bf16 hi/lo split, fp32 accumulate. Double-buffered smem, cp.async W staging.
__global__ __launch_bounds__(256, 1) void pair_mma_kernel(
    const float* __restrict__ A, const float* __restrict__ Bm,
    const float* __restrict__ bf1, const float* __restrict__ bf2,
    float* __restrict__ S2a, float* __restrict__ S2b)
{
    extern __shared__ __align__(16) char smraw[];
    const uint32_t raw = smem_u32(smraw);
    const uint32_t sb = (raw + 127u) & ~127u;
    char* smp = smraw + (sb - raw);

    const int j = blockIdx.x;
    const int half = blockIdx.y;
    const int t = threadIdx.x;
    const int lane = t & 31;
    const int w = t >> 5;
    const int wm = w >> 2;          // 0..1  (m-warp: 64 rows)
    const int wn = w & 3;           // 0..3  (n-warp: 64 cols)

    float* sBB = (float*)(smp + OFF_BB);
    float* sB2 = (float*)(smp + OFF_B2);
    float* sRED = (float*)(smp + OFF_RED);

    sBB[t] = Bm[j * 256 + t] + bf1[t];
    sB2[t] = bf2[t];

    // ldmatrix addressing (XOR swizzle term: (lane&7)*16)
    const uint32_t lx = (uint32_t)(lane & 7) * 16u;
    const uint32_t rowOff = (uint32_t)(lane & 15) * 128u;
    const uint32_t segOff = (uint32_t)(lane >> 4) * 16u;
    const uint32_t wmOff = (uint32_t)(wm * 64) * 128u + rowOff;
    const uint32_t wnOff = (uint32_t)(wn * 64) * 128u + rowOff;

    // A staging coords: thread t handles row ar, k-half akh (32 k values)
    const int ar = t >> 1;
    const int akh = t & 1;
    const uint32_t rbase = (uint32_t)(ar * 128 + akh * 64);
    const uint32_t rxor = (uint32_t)(ar & 7) * 16u;

    float s[16];
#pragma unroll
    for (int q = 0; q < 16; q++) s[q] = 0.f;

    float acc[4][8][4];
#pragma unroll
    for (int mt = 0; mt < 4; mt++)
#pragma unroll
        for (int nt = 0; nt < 8; nt++)
#pragma unroll
            for (int e = 0; e < 4; e++) acc[mt][nt][e] = 0.f;

    __syncthreads();   // sBB ready

    float4 av[8];

    // --- staging helpers (macros to keep everything in-scope) ---
#define STAGE_W_ASYNC(kc_, b_) do { \
        const uint32_t wHiA = sb + OFF_WHI + (uint32_t)(b_) * 32768u; \
        const uint32_t wLoA = sb + OFF_WLO + (uint32_t)(b_) * 32768u; \
        const uint4* srcH = g_Whi4 + (kc_) * 2048; \
        const uint4* srcL = g_Wlo4 + (kc_) * 2048; \
        _Pragma("unroll") \
        for (int r = 0; r < 8; r++) { \
            const int li = r * 256 + t; \
            const int n_ = li >> 3, seg_ = li & 7; \
            const uint32_t sw = ((uint32_t)(n_ * 128 + seg_ * 16)) ^ ((uint32_t)(n_ & 7) * 16u); \
            CP_ASYNC16(wHiA + sw, (const void*)(srcH + li)); \
            CP_ASYNC16(wLoA + sw, (const void*)(srcL + li)); \
        } \
        CP_COMMIT(); \
    } while (0)

#define LOAD_A(it_, kc_) do { \
        const float* ap = A + ((it_) * 128 + ar) * 256 + (kc_) * 64 + akh * 32; \
        _Pragma("unroll") \
        for (int g = 0; g < 4; g++) { \
            av[2 * g]     = *(const float4*)(ap + g * 8); \
            av[2 * g + 1] = *(const float4*)(ap + g * 8 + 4); \
        } \
    } while (0)

#define STORE_A(kc_, b_) do { \
        const float* bbp = sBB + (kc_) * 64 + akh * 32; \
        char* aHi = smp + OFF_AHI + (uint32_t)(b_) * 16384u; \
        char* aLo = smp + OFF_ALO + (uint32_t)(b_) * 16384u; \
        _Pragma("unroll") \
        for (int g = 0; g < 4; g++) { \
            float4 b0 = *(const float4*)(bbp + g * 8); \
            float4 b1 = *(const float4*)(bbp + g * 8 + 4); \
            float f0 = fmaxf(av[2*g].x + b0.x, 0.f), f1 = fmaxf(av[2*g].y + b0.y, 0.f); \
            float f2 = fmaxf(av[2*g].z + b0.z, 0.f), f3 = fmaxf(av[2*g].w + b0.w, 0.f); \
            float f4 = fmaxf(av[2*g+1].x + b1.x, 0.f), f5 = fmaxf(av[2*g+1].y + b1.y, 0.f); \
            float f6 = fmaxf(av[2*g+1].z + b1.z, 0.f), f7 = fmaxf(av[2*g+1].w + b1.w, 0.f); \
            uint4 hp; \
            hp.x = pack_rn2(f0, f1); hp.y = pack_rn2(f2, f3); \
            hp.z = pack_rn2(f4, f5); hp.w = pack_rn2(f6, f7); \
            uint4 lp; \
            lp.x = pack_rn2(f0 - __uint_as_float(hp.x << 16), \
                            f1 - __uint_as_float(hp.x & 0xFFFF0000u)); \
            lp.y = pack_rn2(f2 - __uint_as_float(hp.y << 16), \
                            f3 - __uint_as_float(hp.y & 0xFFFF0000u)); \
            lp.z = pack_rn2(f4 - __uint_as_float(hp.z << 16), \
                            f5 - __uint_as_float(hp.z & 0xFFFF0000u)); \
            lp.w = pack_rn2(f6 - __uint_as_float(hp.w << 16), \
                            f7 - __uint_as_float(hp.w & 0xFFFF0000u)); \
            const uint32_t sw = (rbase + (uint32_t)g * 16u) ^ rxor; \
            *(uint4*)(aHi + sw) = hp; \
            *(uint4*)(aLo + sw) = lp; \
        } \
    } while (0)

    // ---- prologue: stage chunk 0 into buffer 0
    STAGE_W_ASYNC(0, 0);
    LOAD_A(half * 2, 0);
    STORE_A(0, 0);
    CP_WAIT0();
    __syncthreads();

    // ---- main pipeline: 8 chunks (2 i-tiles x 4 k-chunks), 1 sync/chunk
    for (int c = 0; c < 8; c++) {
        const int b = c & 1;

        // prefetch next chunk: async W + A gmem->regs (hidden under MMA)
        if (c < 7) {
            STAGE_W_ASYNC((c + 1) & 3, b ^ 1);
            LOAD_A(half * 2 + ((c + 1) >> 2), (c + 1) & 3);
        }

        // ---- MMA on buffer b: 4 k-steps of 16, 3 passes (hh, lh, hl)
        {
            const uint32_t aRowHi = sb + OFF_AHI + (uint32_t)b * 16384u + wmOff;
            const uint32_t aRowLo = sb + OFF_ALO + (uint32_t)b * 16384u + wmOff;
            const uint32_t wRowHi = sb + OFF_WHI + (uint32_t)b * 32768u + wnOff;
            const uint32_t wRowLo = sb + OFF_WLO + (uint32_t)b * 32768u + wnOff;
#pragma unroll
            for (int ks = 0; ks < 4; ks++) {
                const uint32_t kx = ((uint32_t)(ks * 32) + segOff) ^ lx;
                uint32_t aH[4][4], aL[4][4], wf[4][4];
#pragma unroll
                for (int mt = 0; mt < 4; mt++) ldsm4(aH[mt], aRowHi + mt * 2048 + kx);
#pragma unroll
                for (int np = 0; np < 4; np++) ldsm4(wf[np], wRowHi + np * 2048 + kx);
#pragma unroll
                for (int mt = 0; mt < 4; mt++)
#pragma unroll
                    for (int np = 0; np < 4; np++) {
                        mma16816(acc[mt][2 * np],     aH[mt], wf[np][0], wf[np][2]);
                        mma16816(acc[mt][2 * np + 1], aH[mt], wf[np][1], wf[np][3]);
                    }
#pragma unroll
                for (int mt = 0; mt < 4; mt++) ldsm4(aL[mt], aRowLo + mt * 2048 + kx);
#pragma unroll
                for (int mt = 0; mt < 4; mt++)
#pragma unroll
                    for (int np = 0; np < 4; np++) {
                        mma16816(acc[mt][2 * np],     aL[mt], wf[np][0], wf[np][2]);
                        mma16816(acc[mt][2 * np + 1], aL[mt], wf[np][1], wf[np][3]);
                    }
#pragma unroll
                for (int np = 0; np < 4; np++) ldsm4(wf[np], wRowLo + np * 2048 + kx);
#pragma unroll
                for (int mt = 0; mt < 4; mt++)
#pragma unroll
                    for (int np = 0; np < 4; np++) {
                        mma16816(acc[mt][2 * np],     aH[mt], wf[np][0], wf[np][2]);
                        mma16816(acc[mt][2 * np + 1], aH[mt], wf[np][1], wf[np][3]);
                    }
            }
        }

        // ---- i-tile boundary: fold relu(h2 + bf2) into running sums, reset acc
        if ((c & 3) == 3) {
#pragma unroll
            for (int nt = 0; nt < 8; nt++) {
                const int col = wn * 64 + nt * 8 + (lane & 3) * 2;
                const float b20 = sB2[col], b21 = sB2[col + 1];
                float t0 = 0.f, t1 = 0.f;
#pragma unroll
                for (int mt = 0; mt < 4; mt++) {
                    t0 += fmaxf(acc[mt][nt][0] + b20, 0.f) + fmaxf(acc[mt][nt][2] + b20, 0.f);
                    t1 += fmaxf(acc[mt][nt][1] + b21, 0.f) + fmaxf(acc[mt][nt][3] + b21, 0.f);
                    acc[mt][nt][0] = 0.f; acc[mt][nt][1] = 0.f;
                    acc[mt][nt][2] = 0.f; acc[mt][nt][3] = 0.f;
                }
                s[nt * 2]     += t0;
                s[nt * 2 + 1] += t1;
            }
        }

        // finish next chunk's staging (A convert+STS; wait W cp.async)
        if (c < 7) {
            STORE_A((c + 1) & 3, b ^ 1);
            CP_WAIT0();
        }
        __syncthreads();
    }

    // ---- reduce over lanes with same (lane&3)
#pragma unroll
    for (int q = 0; q < 16; q++) {
        s[q] += __shfl_xor_sync(0xFFFFFFFFu, s[q], 4);
        s[q] += __shfl_xor_sync(0xFFFFFFFFu, s[q], 8);
        s[q] += __shfl_xor_sync(0xFFFFFFFFu, s[q], 16);
    }
    if (lane < 4) {
#pragma unroll
        for (int nt = 0; nt < 8; nt++) {
            const int col = wn * 64 + nt * 8 + lane * 2;
            sRED[wm * 256 + col]     = s[nt * 2];
            sRED[wm * 256 + col + 1] = s[nt * 2 + 1];
        }
    }
    __syncthreads();
    float* dst = half ? S2b : S2a;
    dst[j * 256 + t] = sRED[t] + sRED[256 + t];
}

// ---------------- Wf2 -> bf16 hi/lo chunked prep ----------------
__global__ void prep_w_kernel(const float* __restrict__ Wf2) {
    const int idx = blockIdx.x * 256 + threadIdx.x;   // 65536
    const int n = idx >> 8, k = idx & 255;
    const float v = Wf2[idx];
    const __nv_bfloat16 hb = __float2bfloat16(v);
    const float lf = v - __bfloat162float(hb);
    const int o = (k >> 6) * 16384 + n * 64 + (k & 63);
    ((__nv_bfloat16*)g_Whi4)[o] = hb;
    ((__nv_bfloat16*)g_Wlo4)[o] = __float2bfloat16(lf);
}

// ---------------- fused A/B projection: z=0 -> A, z=1 -> B ----------------
__global__ __launch_bounds__(256) void gemm_ab(
    const float* __restrict__ hid, const float* __restrict__ Wf1)
{
    __shared__ float sX[32][34];
    __shared__ float sW[32][34];
    const int t = threadIdx.x;
    const int m0 = blockIdx.y * 32, n0 = blockIdx.x * 32;
    const float* W = Wf1 + blockIdx.z * 128;
    float* C = blockIdx.z ? g_B : g_A;
    const int lm = t >> 3;
    const int lk = (t & 7) * 4;
    const int tm = (t >> 4) * 2;
    const int tn = (t & 15) * 2;

    float a00 = 0.f, a01 = 0.f, a10 = 0.f, a11 = 0.f;
    float4 xv = *(const float4*)(hid + (m0 + lm) * 128 + lk);
    float4 wv = *(const float4*)(W + (n0 + lm) * 256 + lk);

    for (int c = 0; c < 4; c++) {
        __syncthreads();
        sX[lk + 0][lm] = xv.x; sX[lk + 1][lm] = xv.y;
        sX[lk + 2][lm] = xv.z; sX[lk + 3][lm] = xv.w;
        sW[lk + 0][lm] = wv.x; sW[lk + 1][lm] = wv.y;
        sW[lk + 2][lm] = wv.z; sW[lk + 3][lm] = wv.w;
        __syncthreads();
        if (c < 3) {
            const int ko = (c + 1) * 32 + lk;
            xv = *(const float4*)(hid + (m0 + lm) * 128 + ko);
            wv = *(const float4*)(W + (n0 + lm) * 256 + ko);
        }
#pragma unroll
        for (int kk = 0; kk < 32; kk++) {
            float2 avv = *(const float2*)&sX[kk][tm];
            float2 bvv = *(const float2*)&sW[kk][tn];
            a00 = fmaf(avv.x, bvv.x, a00);
            a01 = fmaf(avv.x, bvv.y, a01);
            a10 = fmaf(avv.y, bvv.x, a10);
            a11 = fmaf(avv.y, bvv.y, a11);
        }
    }
    const int m = m0 + tm, n = n0 + tn;
    C[m * 256 + n] = a00;       C[m * 256 + n + 1] = a01;
    C[(m + 1) * 256 + n] = a10; C[(m + 1) * 256 + n + 1] = a11;
}

// ---------------- small GEMM: C = act(X1@W1^T [+ X2@W2^T] + bScale*b1 [+ b2]) ----------------
__global__ __launch_bounds__(256) void gemm32(
    const float* __restrict__ X1, int ldx1,
    const float* __restrict__ W1, int ldw1, int K1,
    const float* __restrict__ X2, int ldx2,
    const float* __restrict__ W2, int ldw2, int K2,
    const float* __restrict__ b1, const float* __restrict__ b2p,
    float bScale, float* __restrict__ C, int ldc, int act)
{
    __shared__ float sX[32][34];
    __shared__ float sW[32][34];
    const int t = threadIdx.x;
    const int m0 = blockIdx.y * 32, n0 = blockIdx.x * 32;
    const int lm = t >> 3;
    const int lk = (t & 7) * 4;
    const int tm = (t >> 4) * 2;
    const int tn = (t & 15) * 2;

    const int nch1 = K1 >> 5;
    const int nch = nch1 + (X2 ? (K2 >> 5) : 0);

    float a00 = 0.f, a01 = 0.f, a10 = 0.f, a11 = 0.f;
    float4 xv = *(const float4*)(X1 + (m0 + lm) * ldx1 + lk);
    float4 wv = *(const float4*)(W1 + (n0 + lm) * ldw1 + lk);

    for (int c = 0; c < nch; c++) {
        __syncthreads();
        sX[lk + 0][lm] = xv.x; sX[lk + 1][lm] = xv.y;
        sX[lk + 2][lm] = xv.z; sX[lk + 3][lm] = xv.w;
        sW[lk + 0][lm] = wv.x; sW[lk + 1][lm] = wv.y;
        sW[lk + 2][lm] = wv.z; sW[lk + 3][lm] = wv.w;
        __syncthreads();
        const int cn = c + 1;
        if (cn < nch) {
            if (cn < nch1) {
                const int ko = cn * 32 + lk;
                xv = *(const float4*)(X1 + (m0 + lm) * ldx1 + ko);
                wv = *(const float4*)(W1 + (n0 + lm) * ldw1 + ko);
            } else {
                const int ko = (cn - nch1) * 32 + lk;
                xv = *(const float4*)(X2 + (m0 + lm) * ldx2 + ko);
                wv = *(const float4*)(W2 + (n0 + lm) * ldw2 + ko);
            }
        }
#pragma unroll
        for (int kk = 0; kk < 32; kk++) {
            float2 avv = *(const float2*)&sX[kk][tm];
            float2 bvv = *(const float2*)&sW[kk][tn];
            a00 = fmaf(avv.x, bvv.x, a00);
            a01 = fmaf(avv.x, bvv.y, a01);
            a10 = fmaf(avv.y, bvv.x, a10);
            a11 = fmaf(avv.y, bvv.y, a11);
        }
    }
    const int m = m0 + tm, n = n0 + tn;
    float bb0 = 0.f, bb1 = 0.f;
    if (b1)  { bb0 = bScale * b1[n]; bb1 = bScale * b1[n + 1]; }
    if (b2p) { bb0 += b2p[n];        bb1 += b2p[n + 1]; }
    float v00 = a00 + bb0, v01 = a01 + bb1, v10 = a10 + bb0, v11 = a11 + bb1;
    if (act) {
        v00 = fmaxf(v00, 0.f); v01 = fmaxf(v01, 0.f);
        v10 = fmaxf(v10, 0.f); v11 = fmaxf(v11, 0.f);
    }
    C[m * ldc + n] = v00;       C[m * ldc + n + 1] = v01;
    C[(m + 1) * ldc + n] = v10; C[(m + 1) * ldc + n + 1] = v11;
}

// ---------------- LSTM elementwise ----------------
__global__ void lstm_kernel(const float* __restrict__ gates,
                            const float* __restrict__ c0,
                            float* __restrict__ out_h1,
                            float* __restrict__ out_h2,
                            float* __restrict__ out_c)
{
    int idx = blockIdx.x * blockDim.x + threadIdx.x;    // 512*128
    int n = idx >> 7, h = idx & 127;
    const float* gr = gates + n * 512;
    float ig = 1.f / (1.f + expf(-gr[h]));
    float fg = 1.f / (1.f + expf(-gr[128 + h]));
    float gg = tanhf(gr[256 + h]);
    float og = 1.f / (1.f + expf(-gr[384 + h]));
    float c = fg * c0[idx] + ig * gg;
    float hn = og * tanhf(c);
    out_h1[idx] = hn;
    out_h2[idx] = hn;
    out_c[idx]  = c;
}

// ---------------- launch ----------------
extern "C" void kernel_launch(void* const* d_in, const int* in_sizes, int n_in,
                              void* d_out, int out_size)
{
    const float* x    = (const float*)d_in[0];
    const float* hid  = (const float*)d_in[1];
    const float* h0   = (const float*)d_in[2];
    const float* c0   = (const float*)d_in[3];
    const float* Wf1  = (const float*)d_in[4];
    const float* bf1  = (const float*)d_in[5];
    const float* Wf2  = (const float*)d_in[6];
    const float* bf2  = (const float*)d_in[7];
    const float* Wf3  = (const float*)d_in[8];
    const float* bf3  = (const float*)d_in[9];
    const float* Wg1  = (const float*)d_in[10];
    const float* bg1  = (const float*)d_in[11];
    const float* Wg2  = (const float*)d_in[12];
    const float* bg2  = (const float*)d_in[13];
    const float* Wg3  = (const float*)d_in[14];
    const float* bg3  = (const float*)d_in[15];
    const float* W_ih = (const float*)d_in[16];
    const float* W_hh = (const float*)d_in[17];
    const float* b_ih = (const float*)d_in[18];
    const float* b_hh = (const float*)d_in[19];
    const float* Wo1  = (const float*)d_in[20];
    const float* bo1  = (const float*)d_in[21];
    const float* Wo2  = (const float*)d_in[22];
    const float* bo2  = (const float*)d_in[23];
    float* out = (float*)d_out;

    float *pA, *pS2a, *pS2b, *psumm, *pg1, *pg2, *pig, *pgates, *po1;
    cudaGetSymbolAddress((void**)&pA,     g_A);
    cudaGetSymbolAddress((void**)&pS2a,   g_S2a);
    cudaGetSymbolAddress((void**)&pS2b,   g_S2b);
    cudaGetSymbolAddress((void**)&psumm,  g_summ);
    cudaGetSymbolAddress((void**)&pg1,    g_g1);
    cudaGetSymbolAddress((void**)&pg2,    g_g2);
    cudaGetSymbolAddress((void**)&pig,    g_ig);
    cudaGetSymbolAddress((void**)&pgates, g_gates);
    cudaGetSymbolAddress((void**)&po1,    g_o1);
    float* pB;
    cudaGetSymbolAddress((void**)&pB,     g_B);

    cudaFuncSetAttribute(pair_mma_kernel, cudaFuncAttributeMaxDynamicSharedMemorySize, PAIR_DYN_SMEM);

    dim3 blk(256);

    // Wf2 bf16 hi/lo prep (chunked layout)
    prep_w_kernel<<<256, blk>>>(Wf2);

    // A = hidden @ Wf1[:, :128]^T ; B = hidden @ Wf1[:, 128:]^T  (one launch)
    gemm_ab<<<dim3(8, 16, 2), blk>>>(hid, Wf1);

    // S2 halves: sum over i in [0,256) -> S2a, [256,512) -> S2b
    pair_mma_kernel<<<dim3(512, 2), blk, PAIR_DYN_SMEM>>>(pA, pB, bf1, bf2, pS2a, pS2b);

    // sum_messages = (S2a + S2b) @ Wf3^T + 512*bf3   (dual-input combine)
    gemm32<<<dim3(4, 16), blk>>>(pS2a, 256, Wf3, 256, 256, pS2b, 256, Wf3, 256, 256,
                                 bf3, nullptr, 512.f, psumm, 128, 0);

    // g1 = relu(x@Wg1a^T + summ@Wg1b^T + bg1)   (fused concat)
    gemm32<<<dim3(8, 16), blk>>>(x, 128, Wg1, 256, 128, psumm, 128, Wg1 + 128, 256, 128,
                                 bg1, nullptr, 1.f, pg1, 256, 1);
    // g2 = relu(g1@Wg2^T + bg2)
    gemm32<<<dim3(8, 16), blk>>>(pg1, 256, Wg2, 256, 256, nullptr, 0, nullptr, 0, 0,
                                 bg2, nullptr, 1.f, pg2, 256, 1);
    // input_g = g2@Wg3^T + bg3
    gemm32<<<dim3(4, 16), blk>>>(pg2, 256, Wg3, 256, 256, nullptr, 0, nullptr, 0, 0,
                                 bg3, nullptr, 1.f, pig, 128, 0);

    // gates = ig@W_ih^T + h0@W_hh^T + b_ih + b_hh   (fused)
    gemm32<<<dim3(16, 16), blk>>>(pig, 128, W_ih, 128, 128, h0, 128, W_hh, 128, 128,
                                  b_ih, b_hh, 1.f, pgates, 512, 0);
    lstm_kernel<<<256, blk>>>(pgates, c0, out + 32768, out + 98304, out + 163840);

    // o-MLP
    gemm32<<<dim3(8, 16), blk>>>(out + 32768, 128, Wo1, 128, 128, nullptr, 0, nullptr, 0, 0,
                                 bo1, nullptr, 1.f, po1, 256, 1);
    gemm32<<<dim3(2, 16), blk>>>(po1, 256, Wo2, 256, 256, nullptr, 0, nullptr, 0, 0,
                                 bo2, nullptr, 1.f, out, 64, 0);
}

// round 6
// speedup vs baseline: 1.8241x; 1.8241x over previous
#include <cuda_runtime.h>
#include <cuda_bf16.h>
#include <cstdint>

#define NN 512

// ---------------- scratch (no allocations allowed) ----------------
__device__ float g_A[NN * 256];
__device__ float g_B[NN * 256];
__device__ float g_S2a[NN * 256];
__device__ float g_S2b[NN * 256];
__device__ float g_summ[NN * 128];
__device__ float g_g1[NN * 256];
__device__ float g_g2[NN * 256];
__device__ float g_ig[NN * 128];
__device__ float g_gates[NN * 512];
__device__ float g_o1[NN * 256];
// Wf2 split into bf16 hi/lo, chunked layout [kc][n][64]
__device__ uint4 g_Whi4[8192];
__device__ uint4 g_Wlo4[8192];

// ================= helpers =================
__device__ __forceinline__ uint32_t smem_u32(const void* p) {
    uint32_t a;
    asm("{ .reg .u64 t; cvta.to.shared.u64 t, %1; cvt.u32.u64 %0, t; }" : "=r"(a) : "l"(p));
    return a;
}

__device__ __forceinline__ void ldsm4(uint32_t (&r)[4], uint32_t addr) {
    asm volatile("ldmatrix.sync.aligned.m8n8.x4.shared.b16 {%0,%1,%2,%3}, [%4];"
        : "=r"(r[0]), "=r"(r[1]), "=r"(r[2]), "=r"(r[3]) : "r"(addr));
}

__device__ __forceinline__ void mma16816(float (&d)[4], const uint32_t (&a)[4],
                                         uint32_t b0, uint32_t b1) {
    asm volatile(
        "mma.sync.aligned.m16n8k16.row.col.f32.bf16.bf16.f32 "
        "{%0,%1,%2,%3}, {%4,%5,%6,%7}, {%8,%9}, {%0,%1,%2,%3};"
        : "+f"(d[0]), "+f"(d[1]), "+f"(d[2]), "+f"(d[3])
        : "r"(a[0]), "r"(a[1]), "r"(a[2]), "r"(a[3]), "r"(b0), "r"(b1));
}

__device__ __forceinline__ uint32_t pack_rn2(float f0, float f1) {
    uint32_t r; asm("cvt.rn.bf16x2.f32 %0, %1, %2;" : "=r"(r) : "f"(f1), "f"(f0));
    return r;
}

#define CP_ASYNC16(dst, src) \
    asm volatile("cp.async.cg.shared.global [%0], [%1], 16;" :: "r"(dst), "l"(src))
#define CP_COMMIT() asm volatile("cp.async.commit_group;" ::: "memory")
#define CP_WAIT0()  asm volatile("cp.async.wait_group 0;"  ::: "memory")

// ================= pair kernel smem layout (byte offsets) =================
// W hi/lo: double-buffered; raw A fp32: double-buffered; split A hi/lo: single.
#define OFF_WHI 0u         // 2 x 32768
#define OFF_WLO 65536u     // 2 x 32768
#define OFF_RAW 131072u    // 2 x 32768 (raw A fp32, linear [row][kseg])
#define OFF_AHI 196608u    // 16384 (split hi, swizzled)
#define OFF_ALO 212992u    // 16384
#define OFF_BB  229376u    // 1024
#define OFF_B2  230400u    // 1024
#define PAIR_DYN_SMEM (231424u + 128u)

// ---------------- pairwise HMMA kernel ----------------
// grid (512, 2): j = blockIdx.x, half = blockIdx.y (i-rows [half*256, half*256+256))
// S2half[j,n] = sum_{i in half} relu( relu(A[i]+B[j]+bf1) @ Wf2^T + bf2 )[n]
// 3-pass bf16 hi/lo split, fp32 accumulate. cp.async smem pipeline, no register prefetch.
__global__ __launch_bounds__(256, 1) void pair_mma_kernel(
    const float* __restrict__ A, const float* __restrict__ Bm,
    const float* __restrict__ bf1, const float* __restrict__ bf2,
    float* __restrict__ S2a, float* __restrict__ S2b)
{
    extern __shared__ __align__(16) char smraw[];
    const uint32_t raw0 = smem_u32(smraw);
    const uint32_t sb = (raw0 + 127u) & ~127u;
    char* smp = smraw + (sb - raw0);

    const int j = blockIdx.x;
    const int half = blockIdx.y;
    const int t = threadIdx.x;
    const int lane = t & 31;
    const int w = t >> 5;
    const int wm = w >> 2;          // 0..1  (m-warp: 64 rows)
    const int wn = w & 3;           // 0..3  (n-warp: 64 cols)

    float* sBB = (float*)(smp + OFF_BB);
    float* sB2 = (float*)(smp + OFF_B2);

    sBB[t] = Bm[j * 256 + t] + bf1[t];
    sB2[t] = bf2[t];

    // ldmatrix addressing (XOR swizzle term: (lane&7)*16)
    const uint32_t lx = (uint32_t)(lane & 7) * 16u;
    const uint32_t rowOff = (uint32_t)(lane & 15) * 128u;
    const uint32_t segOff = (uint32_t)(lane >> 4) * 16u;
    const uint32_t wmOff = (uint32_t)(wm * 64) * 128u + rowOff;
    const uint32_t wnOff = (uint32_t)(wn * 64) * 128u + rowOff;

    float s[16];
#pragma unroll
    for (int q = 0; q < 16; q++) s[q] = 0.f;

    float acc[4][8][4];
#pragma unroll
    for (int mt = 0; mt < 4; mt++)
#pragma unroll
        for (int nt = 0; nt < 8; nt++)
#pragma unroll
            for (int e = 0; e < 4; e++) acc[mt][nt][e] = 0.f;

    // ---- staging macros (cp.async only; no persistent registers) ----
#define STAGE_W_ASYNC(kc_, wb_) do { \
        const uint32_t wHiA = sb + OFF_WHI + (uint32_t)(wb_) * 32768u; \
        const uint32_t wLoA = sb + OFF_WLO + (uint32_t)(wb_) * 32768u; \
        const uint4* srcH = g_Whi4 + (kc_) * 2048; \
        const uint4* srcL = g_Wlo4 + (kc_) * 2048; \
        _Pragma("unroll") \
        for (int r = 0; r < 8; r++) { \
            const int li = r * 256 + t; \
            const int n_ = li >> 3, seg_ = li & 7; \
            const uint32_t sw = ((uint32_t)(n_ * 128 + seg_ * 16)) ^ ((uint32_t)(n_ & 7) * 16u); \
            CP_ASYNC16(wHiA + sw, (const void*)(srcH + li)); \
            CP_ASYNC16(wLoA + sw, (const void*)(srcL + li)); \
        } \
    } while (0)

#define STAGE_A_ASYNC(it_, kc_, rb_) do { \
        const uint32_t rawA = sb + OFF_RAW + (uint32_t)(rb_) * 32768u; \
        const float* srcA = A + ((it_) * 128) * 256 + (kc_) * 64; \
        _Pragma("unroll") \
        for (int r = 0; r < 8; r++) { \
            const int li = r * 256 + t; \
            const int row_ = li >> 4, seg_ = li & 15; \
            CP_ASYNC16(rawA + (uint32_t)li * 16u, (const void*)(srcA + row_ * 256 + seg_ * 4)); \
        } \
    } while (0)

    // convert raw fp32 chunk -> relu(+bb) -> split hi/lo bf16 (swizzled)
#define CONVERT_A(kc_, rb_) do { \
        const float* rawp = (const float*)(smp + OFF_RAW + (uint32_t)(rb_) * 32768u); \
        char* aHi = smp + OFF_AHI; \
        char* aLo = smp + OFF_ALO; \
        _Pragma("unroll") \
        for (int r = 0; r < 8; r++) { \
            const int li = r * 256 + t; \
            const int row_ = li >> 4, seg_ = li & 15; \
            float4 v = *(const float4*)(rawp + li * 4); \
            float4 bbv = *(const float4*)(sBB + (kc_) * 64 + seg_ * 4); \
            float f0 = fmaxf(v.x + bbv.x, 0.f), f1 = fmaxf(v.y + bbv.y, 0.f); \
            float f2 = fmaxf(v.z + bbv.z, 0.f), f3 = fmaxf(v.w + bbv.w, 0.f); \
            uint2 hp, lp; \
            hp.x = pack_rn2(f0, f1); hp.y = pack_rn2(f2, f3); \
            lp.x = pack_rn2(f0 - __uint_as_float(hp.x << 16), \
                            f1 - __uint_as_float(hp.x & 0xFFFF0000u)); \
            lp.y = pack_rn2(f2 - __uint_as_float(hp.y << 16), \
                            f3 - __uint_as_float(hp.y & 0xFFFF0000u)); \
            const uint32_t off_ = (uint32_t)(row_ * 128 + seg_ * 8); \
            const uint32_t sw = off_ ^ ((uint32_t)(row_ & 7) * 16u); \
            *(uint2*)(aHi + sw) = hp; \
            *(uint2*)(aLo + sw) = lp; \
        } \
    } while (0)

    // ---- prologue: stage chunk 0, convert
    STAGE_W_ASYNC(0, 0);
    STAGE_A_ASYNC(half * 2, 0, 0);
    CP_COMMIT();
    __syncthreads();           // sBB/sB2 visible
    CP_WAIT0();
    CONVERT_A(0, 0);
    __syncthreads();           // split + W[0] ready

    // ---- main pipeline: 8 chunks (2 i-tiles x 4 k-chunks)
#pragma unroll 1
    for (int c = 0; c < 8; c++) {
        const int b = c & 1;

        // prefetch chunk c+1 (fills W[b^1], raw[b^1]) — overlaps MMA below
        if (c < 7) {
            STAGE_W_ASYNC((c + 1) & 3, b ^ 1);
            STAGE_A_ASYNC(half * 2 + ((c + 1) >> 2), (c + 1) & 3, b ^ 1);
            CP_COMMIT();
        }

        // ---- MMA on split + W[b]: 4 k-steps of 16, 3 passes (hh, lh, hl)
        {
            const uint32_t aRowHi = sb + OFF_AHI + wmOff;
            const uint32_t aRowLo = sb + OFF_ALO + wmOff;
            const uint32_t wRowHi = sb + OFF_WHI + (uint32_t)b * 32768u + wnOff;
            const uint32_t wRowLo = sb + OFF_WLO + (uint32_t)b * 32768u + wnOff;
#pragma unroll
            for (int ks = 0; ks < 4; ks++) {
                const uint32_t kx = ((uint32_t)(ks * 32) + segOff) ^ lx;
                uint32_t aH[4][4], aL[4][4], wf[4][4];
#pragma unroll
                for (int mt = 0; mt < 4; mt++) ldsm4(aH[mt], aRowHi + mt * 2048 + kx);
#pragma unroll
                for (int np = 0; np < 4; np++) ldsm4(wf[np], wRowHi + np * 2048 + kx);
#pragma unroll
                for (int mt = 0; mt < 4; mt++)
#pragma unroll
                    for (int np = 0; np < 4; np++) {
                        mma16816(acc[mt][2 * np],     aH[mt], wf[np][0], wf[np][2]);
                        mma16816(acc[mt][2 * np + 1], aH[mt], wf[np][1], wf[np][3]);
                    }
#pragma unroll
                for (int mt = 0; mt < 4; mt++) ldsm4(aL[mt], aRowLo + mt * 2048 + kx);
#pragma unroll
                for (int mt = 0; mt < 4; mt++)
#pragma unroll
                    for (int np = 0; np < 4; np++) {
                        mma16816(acc[mt][2 * np],     aL[mt], wf[np][0], wf[np][2]);
                        mma16816(acc[mt][2 * np + 1], aL[mt], wf[np][1], wf[np][3]);
                    }
#pragma unroll
                for (int np = 0; np < 4; np++) ldsm4(wf[np], wRowLo + np * 2048 + kx);
#pragma unroll
                for (int mt = 0; mt < 4; mt++)
#pragma unroll
                    for (int np = 0; np < 4; np++) {
                        mma16816(acc[mt][2 * np],     aH[mt], wf[np][0], wf[np][2]);
                        mma16816(acc[mt][2 * np + 1], aH[mt], wf[np][1], wf[np][3]);
                    }
            }
        }

        __syncthreads();       // ldsm of chunk c done: split free to overwrite

        // ---- boundary: finish prefetch, convert next A chunk into split
        if (c < 7) {
            CP_WAIT0();
            CONVERT_A((c + 1) & 3, b ^ 1);
        }

        // ---- i-tile boundary: fold relu(h2 + bf2) into running sums
        if ((c & 3) == 3) {
#pragma unroll
            for (int nt = 0; nt < 8; nt++) {
                const int col = wn * 64 + nt * 8 + (lane & 3) * 2;
                const float b20 = sB2[col], b21 = sB2[col + 1];
                float t0 = 0.f, t1 = 0.f;
#pragma unroll
                for (int mt = 0; mt < 4; mt++) {
                    t0 += fmaxf(acc[mt][nt][0] + b20, 0.f) + fmaxf(acc[mt][nt][2] + b20, 0.f);
                    t1 += fmaxf(acc[mt][nt][1] + b21, 0.f) + fmaxf(acc[mt][nt][3] + b21, 0.f);
                    acc[mt][nt][0] = 0.f; acc[mt][nt][1] = 0.f;
                    acc[mt][nt][2] = 0.f; acc[mt][nt][3] = 0.f;
                }
                s[nt * 2]     += t0;
                s[nt * 2 + 1] += t1;
            }
        }

        __syncthreads();       // split writes visible before next chunk's ldsm
    }

    // ---- reduce over lanes with same (lane&3) (rows live in lane>>2)
#pragma unroll
    for (int q = 0; q < 16; q++) {
        s[q] += __shfl_xor_sync(0xFFFFFFFFu, s[q], 4);
        s[q] += __shfl_xor_sync(0xFFFFFFFFu, s[q], 8);
        s[q] += __shfl_xor_sync(0xFFFFFFFFu, s[q], 16);
    }
    float* sRED = (float*)(smp + OFF_RAW);   // alias raw buffer (loop finished)
    if (lane < 4) {
#pragma unroll
        for (int nt = 0; nt < 8; nt++) {
            const int col = wn * 64 + nt * 8 + lane * 2;
            sRED[wm * 256 + col]     = s[nt * 2];
            sRED[wm * 256 + col + 1] = s[nt * 2 + 1];
        }
    }
    __syncthreads();
    float* dst = half ? S2b : S2a;
    dst[j * 256 + t] = sRED[t] + sRED[256 + t];
}

// ---------------- Wf2 -> bf16 hi/lo chunked prep ----------------
__global__ void prep_w_kernel(const float* __restrict__ Wf2) {
    const int idx = blockIdx.x * 256 + threadIdx.x;   // 65536
    const int n = idx >> 8, k = idx & 255;
    const float v = Wf2[idx];
    const __nv_bfloat16 hb = __float2bfloat16(v);
    const float lf = v - __bfloat162float(hb);
    const int o = (k >> 6) * 16384 + n * 64 + (k & 63);
    ((__nv_bfloat16*)g_Whi4)[o] = hb;
    ((__nv_bfloat16*)g_Wlo4)[o] = __float2bfloat16(lf);
}

// ---------------- fused A/B projection: z=0 -> A, z=1 -> B ----------------
__global__ __launch_bounds__(256) void gemm_ab(
    const float* __restrict__ hid, const float* __restrict__ Wf1)
{
    __shared__ float sX[32][34];
    __shared__ float sW[32][34];
    const int t = threadIdx.x;
    const int m0 = blockIdx.y * 32, n0 = blockIdx.x * 32;
    const float* W = Wf1 + blockIdx.z * 128;
    float* C = blockIdx.z ? g_B : g_A;
    const int lm = t >> 3;
    const int lk = (t & 7) * 4;
    const int tm = (t >> 4) * 2;
    const int tn = (t & 15) * 2;

    float a00 = 0.f, a01 = 0.f, a10 = 0.f, a11 = 0.f;
    float4 xv = *(const float4*)(hid + (m0 + lm) * 128 + lk);
    float4 wv = *(const float4*)(W + (n0 + lm) * 256 + lk);

    for (int c = 0; c < 4; c++) {
        __syncthreads();
        sX[lk + 0][lm] = xv.x; sX[lk + 1][lm] = xv.y;
        sX[lk + 2][lm] = xv.z; sX[lk + 3][lm] = xv.w;
        sW[lk + 0][lm] = wv.x; sW[lk + 1][lm] = wv.y;
        sW[lk + 2][lm] = wv.z; sW[lk + 3][lm] = wv.w;
        __syncthreads();
        if (c < 3) {
            const int ko = (c + 1) * 32 + lk;
            xv = *(const float4*)(hid + (m0 + lm) * 128 + ko);
            wv = *(const float4*)(W + (n0 + lm) * 256 + ko);
        }
#pragma unroll
        for (int kk = 0; kk < 32; kk++) {
            float2 avv = *(const float2*)&sX[kk][tm];
            float2 bvv = *(const float2*)&sW[kk][tn];
            a00 = fmaf(avv.x, bvv.x, a00);
            a01 = fmaf(avv.x, bvv.y, a01);
            a10 = fmaf(avv.y, bvv.x, a10);
            a11 = fmaf(avv.y, bvv.y, a11);
        }
    }
    const int m = m0 + tm, n = n0 + tn;
    C[m * 256 + n] = a00;       C[m * 256 + n + 1] = a01;
    C[(m + 1) * 256 + n] = a10; C[(m + 1) * 256 + n + 1] = a11;
}

// ---------------- small GEMM: C = act(X1@W1^T [+ X2@W2^T] + bScale*b1 [+ b2]) ----------------
__global__ __launch_bounds__(256) void gemm32(
    const float* __restrict__ X1, int ldx1,
    const float* __restrict__ W1, int ldw1, int K1,
    const float* __restrict__ X2, int ldx2,
    const float* __restrict__ W2, int ldw2, int K2,
    const float* __restrict__ b1, const float* __restrict__ b2p,
    float bScale, float* __restrict__ C, int ldc, int act)
{
    __shared__ float sX[32][34];
    __shared__ float sW[32][34];
    const int t = threadIdx.x;
    const int m0 = blockIdx.y * 32, n0 = blockIdx.x * 32;
    const int lm = t >> 3;
    const int lk = (t & 7) * 4;
    const int tm = (t >> 4) * 2;
    const int tn = (t & 15) * 2;

    const int nch1 = K1 >> 5;
    const int nch = nch1 + (X2 ? (K2 >> 5) : 0);

    float a00 = 0.f, a01 = 0.f, a10 = 0.f, a11 = 0.f;
    float4 xv = *(const float4*)(X1 + (m0 + lm) * ldx1 + lk);
    float4 wv = *(const float4*)(W1 + (n0 + lm) * ldw1 + lk);

    for (int c = 0; c < nch; c++) {
        __syncthreads();
        sX[lk + 0][lm] = xv.x; sX[lk + 1][lm] = xv.y;
        sX[lk + 2][lm] = xv.z; sX[lk + 3][lm] = xv.w;
        sW[lk + 0][lm] = wv.x; sW[lk + 1][lm] = wv.y;
        sW[lk + 2][lm] = wv.z; sW[lk + 3][lm] = wv.w;
        __syncthreads();
        const int cn = c + 1;
        if (cn < nch) {
            if (cn < nch1) {
                const int ko = cn * 32 + lk;
                xv = *(const float4*)(X1 + (m0 + lm) * ldx1 + ko);
                wv = *(const float4*)(W1 + (n0 + lm) * ldw1 + ko);
            } else {
                const int ko = (cn - nch1) * 32 + lk;
                xv = *(const float4*)(X2 + (m0 + lm) * ldx2 + ko);
                wv = *(const float4*)(W2 + (n0 + lm) * ldw2 + ko);
            }
        }
#pragma unroll
        for (int kk = 0; kk < 32; kk++) {
            float2 avv = *(const float2*)&sX[kk][tm];
            float2 bvv = *(const float2*)&sW[kk][tn];
            a00 = fmaf(avv.x, bvv.x, a00);
            a01 = fmaf(avv.x, bvv.y, a01);
            a10 = fmaf(avv.y, bvv.x, a10);
            a11 = fmaf(avv.y, bvv.y, a11);
        }
    }
    const int m = m0 + tm, n = n0 + tn;
    float bb0 = 0.f, bb1 = 0.f;
    if (b1)  { bb0 = bScale * b1[n]; bb1 = bScale * b1[n + 1]; }
    if (b2p) { bb0 += b2p[n];        bb1 += b2p[n + 1]; }
    float v00 = a00 + bb0, v01 = a01 + bb1, v10 = a10 + bb0, v11 = a11 + bb1;
    if (act) {
        v00 = fmaxf(v00, 0.f); v01 = fmaxf(v01, 0.f);
        v10 = fmaxf(v10, 0.f); v11 = fmaxf(v11, 0.f);
    }
    C[m * ldc + n] = v00;       C[m * ldc + n + 1] = v01;
    C[(m + 1) * ldc + n] = v10; C[(m + 1) * ldc + n + 1] = v11;
}

// ---------------- LSTM elementwise ----------------
__global__ void lstm_kernel(const float* __restrict__ gates,
                            const float* __restrict__ c0,
                            float* __restrict__ out_h1,
                            float* __restrict__ out_h2,
                            float* __restrict__ out_c)
{
    int idx = blockIdx.x * blockDim.x + threadIdx.x;    // 512*128
    int n = idx >> 7, h = idx & 127;
    const float* gr = gates + n * 512;
    float ig = 1.f / (1.f + expf(-gr[h]));
    float fg = 1.f / (1.f + expf(-gr[128 + h]));
    float gg = tanhf(gr[256 + h]);
    float og = 1.f / (1.f + expf(-gr[384 + h]));
    float c = fg * c0[idx] + ig * gg;
    float hn = og * tanhf(c);
    out_h1[idx] = hn;
    out_h2[idx] = hn;
    out_c[idx]  = c;
}

// ---------------- launch ----------------
extern "C" void kernel_launch(void* const* d_in, const int* in_sizes, int n_in,
                              void* d_out, int out_size)
{
    const float* x    = (const float*)d_in[0];
    const float* hid  = (const float*)d_in[1];
    const float* h0   = (const float*)d_in[2];
    const float* c0   = (const float*)d_in[3];
    const float* Wf1  = (const float*)d_in[4];
    const float* bf1  = (const float*)d_in[5];
    const float* Wf2  = (const float*)d_in[6];
    const float* bf2  = (const float*)d_in[7];
    const float* Wf3  = (const float*)d_in[8];
    const float* bf3  = (const float*)d_in[9];
    const float* Wg1  = (const float*)d_in[10];
    const float* bg1  = (const float*)d_in[11];
    const float* Wg2  = (const float*)d_in[12];
    const float* bg2  = (const float*)d_in[13];
    const float* Wg3  = (const float*)d_in[14];
    const float* bg3  = (const float*)d_in[15];
    const float* W_ih = (const float*)d_in[16];
    const float* W_hh = (const float*)d_in[17];
    const float* b_ih = (const float*)d_in[18];
    const float* b_hh = (const float*)d_in[19];
    const float* Wo1  = (const float*)d_in[20];
    const float* bo1  = (const float*)d_in[21];
    const float* Wo2  = (const float*)d_in[22];
    const float* bo2  = (const float*)d_in[23];
    float* out = (float*)d_out;

    float *pA, *pB, *pS2a, *pS2b, *psumm, *pg1, *pg2, *pig, *pgates, *po1;
    cudaGetSymbolAddress((void**)&pA,     g_A);
    cudaGetSymbolAddress((void**)&pB,     g_B);
    cudaGetSymbolAddress((void**)&pS2a,   g_S2a);
    cudaGetSymbolAddress((void**)&pS2b,   g_S2b);
    cudaGetSymbolAddress((void**)&psumm,  g_summ);
    cudaGetSymbolAddress((void**)&pg1,    g_g1);
    cudaGetSymbolAddress((void**)&pg2,    g_g2);
    cudaGetSymbolAddress((void**)&pig,    g_ig);
    cudaGetSymbolAddress((void**)&pgates, g_gates);
    cudaGetSymbolAddress((void**)&po1,    g_o1);

    cudaFuncSetAttribute(pair_mma_kernel, cudaFuncAttributeMaxDynamicSharedMemorySize, PAIR_DYN_SMEM);

    dim3 blk(256);

    // Wf2 bf16 hi/lo prep (chunked layout)
    prep_w_kernel<<<256, blk>>>(Wf2);

    // A = hidden @ Wf1[:, :128]^T ; B = hidden @ Wf1[:, 128:]^T  (one launch)
    gemm_ab<<<dim3(8, 16, 2), blk>>>(hid, Wf1);

    // S2 halves: sum over i in [0,256) -> S2a, [256,512) -> S2b
    pair_mma_kernel<<<dim3(512, 2), blk, PAIR_DYN_SMEM>>>(pA, pB, bf1, bf2, pS2a, pS2b);

    // sum_messages = (S2a + S2b) @ Wf3^T + 512*bf3   (dual-input combine)
    gemm32<<<dim3(4, 16), blk>>>(pS2a, 256, Wf3, 256, 256, pS2b, 256, Wf3, 256, 256,
                                 bf3, nullptr, 512.f, psumm, 128, 0);

    // g1 = relu(x@Wg1a^T + summ@Wg1b^T + bg1)   (fused concat)
    gemm32<<<dim3(8, 16), blk>>>(x, 128, Wg1, 256, 128, psumm, 128, Wg1 + 128, 256, 128,
                                 bg1, nullptr, 1.f, pg1, 256, 1);
    // g2 = relu(g1@Wg2^T + bg2)
    gemm32<<<dim3(8, 16), blk>>>(pg1, 256, Wg2, 256, 256, nullptr, 0, nullptr, 0, 0,
                                 bg2, nullptr, 1.f, pg2, 256, 1);
    // input_g = g2@Wg3^T + bg3
    gemm32<<<dim3(4, 16), blk>>>(pg2, 256, Wg3, 256, 256, nullptr, 0, nullptr, 0, 0,
                                 bg3, nullptr, 1.f, pig, 128, 0);

    // gates = ig@W_ih^T + h0@W_hh^T + b_ih + b_hh   (fused)
    gemm32<<<dim3(16, 16), blk>>>(pig, 128, W_ih, 128, 128, h0, 128, W_hh, 128, 128,
                                  b_ih, b_hh, 1.f, pgates, 512, 0);
    lstm_kernel<<<256, blk>>>(pgates, c0, out + 32768, out + 98304, out + 163840);

    // o-MLP
    gemm32<<<dim3(8, 16), blk>>>(out + 32768, 128, Wo1, 128, 128, nullptr, 0, nullptr, 0, 0,
                                 bo1, nullptr, 1.f, po1, 256, 1);
    gemm32<<<dim3(2, 16), blk>>>(po1, 256, Wo2, 256, 256, nullptr, 0, nullptr, 0, 0,
                                 bo2, nullptr, 1.f, out, 64, 0);
}